// round 3
// baseline (speedup 1.0000x reference)
#include <cuda_runtime.h>
#include <math.h>

#define NPOS 512
#define NALL 1024
#define DIM  512
#define EPSV 1e-5f
#define COSEPS 1e-8f
#define TILE 64
#define DK   32          // floats per chunk (16 k-pairs)
#define NKP  16          // k-pairs per chunk
#define SROW 66          // float2 per smem row (64 data + 2 pad); 528B, 16B-aligned

// ---------------- device scratch ----------------
__device__ float g_rnorm[NALL];
__device__ float g_t1[NPOS];
__device__ float g_t2[NALL];
__device__ float g_deno[NPOS];
__device__ float g_total;
__device__ unsigned g_negdone;
__device__ unsigned g_alldone;

__device__ __forceinline__ float warp_sum(float v) {
#pragma unroll
    for (int o = 16; o; o >>= 1) v += __shfl_xor_sync(0xffffffffu, v, o);
    return v;
}

// packed fp32x2 fma (SASS FFMA2)
__device__ __forceinline__ unsigned long long ff2(unsigned long long a,
                                                  unsigned long long b,
                                                  unsigned long long c) {
    unsigned long long d;
    asm("fma.rn.f32x2 %0, %1, %2, %3;" : "=l"(d) : "l"(a), "l"(b), "l"(c));
    return d;
}
__device__ __forceinline__ float lo2(unsigned long long v) { return __uint_as_float((unsigned)v); }
__device__ __forceinline__ float hi2(unsigned long long v) { return __uint_as_float((unsigned)(v >> 32)); }

__device__ __forceinline__ float sp(float x) {   // softplus, stable
    return fmaxf(x, 0.f) + log1pf(expf(-fabsf(x)));
}

// ---------------- kernel 1: per-row norm, t1, t2 (+ scratch init) ----------------
__global__ void row_kernel(const float* __restrict__ pos,
                           const float* __restrict__ neg,
                           const float* __restrict__ w) {
    int row = blockIdx.x;                       // 0..1023
    int t = threadIdx.x;                        // 128
    if (t == 0) {
        if (row < NPOS) g_deno[row] = 0.f;
        if (row == 0) { g_total = 0.f; g_negdone = 0u; g_alldone = 0u; }
    }
    const float* src = (row < NPOS) ? (pos + row * DIM) : (neg + (row - NPOS) * DIM);
    float4 v  = ((const float4*)src)[t];
    float4 u1 = ((const float4*)w)[t];
    float4 u2 = ((const float4*)(w + DIM))[t];
    float ss = v.x * v.x; ss = fmaf(v.y, v.y, ss); ss = fmaf(v.z, v.z, ss); ss = fmaf(v.w, v.w, ss);
    float d1 = v.x * u1.x; d1 = fmaf(v.y, u1.y, d1); d1 = fmaf(v.z, u1.z, d1); d1 = fmaf(v.w, u1.w, d1);
    float d2 = v.x * u2.x; d2 = fmaf(v.y, u2.y, d2); d2 = fmaf(v.z, u2.z, d2); d2 = fmaf(v.w, u2.w, d2);
    ss = warp_sum(ss); d1 = warp_sum(d1); d2 = warp_sum(d2);
    __shared__ float red[3][4];
    int wid = t >> 5, lid = t & 31;
    if (lid == 0) { red[0][wid] = ss; red[1][wid] = d1; red[2][wid] = d2; }
    __syncthreads();
    if (t == 0) {
        float S  = red[0][0] + red[0][1] + red[0][2] + red[0][3];
        float D1 = red[1][0] + red[1][1] + red[1][2] + red[1][3];
        float D2 = red[2][0] + red[2][1] + red[2][2] + red[2][3];
        g_rnorm[row] = 1.f / fmaxf(sqrtf(S), COSEPS);
        g_t2[row] = D2;
        if (row < NPOS) g_t1[row] = D1;
    }
}

// ---------------- kernel 2: fused pair kernel ----------------
// grid (16, 8): bx<8 -> pos-vs-pos half (loss1 + bce), bx>=8 -> pos-vs-neg (deno + bce)
__global__ void __launch_bounds__(256, 1) pair_kernel(
    const float* __restrict__ pos, const float* __restrict__ neg,
    const float* __restrict__ w, const float* __restrict__ bptr,
    float* __restrict__ out)
{
    __shared__ __align__(16) float2 sA[NKP][SROW];  // [k-pair][row]
    __shared__ __align__(16) float2 sB[NKP][SROW];
    __shared__ float2 sW2[NKP];
    __shared__ float sRed[8];

    const int t  = threadIdx.x;
    const int tx = t & 15, ty = t >> 4;
    const int n0 = blockIdx.y * TILE;
    const int m0 = blockIdx.x * TILE;
    const bool pos_half = (m0 < NPOS);
    const float* Bsrc = pos_half ? pos : neg;
    const int mrow0 = pos_half ? m0 : (m0 - NPOS);
    const float* w3 = w + 2 * DIM;

    const int lc2 = t & 15;      // k-pair index within chunk
    const int lr  = t >> 4;      // row group (0..15)

    const unsigned long long NEG1 = 0xBF800000BF800000ULL;
    const unsigned long long ABSM = 0x7FFFFFFF7FFFFFFFULL;

    unsigned long long dot2[4][4], t32[4][4];
#pragma unroll
    for (int i = 0; i < 4; i++)
#pragma unroll
        for (int j = 0; j < 4; j++) { dot2[i][j] = 0ULL; t32[i][j] = 0ULL; }

    // register prefetch of one chunk (4 rows per array per thread)
    float2 pfA[4], pfB[4], pfW;
#define LOADC(D0) do {                                                        \
    _Pragma("unroll")                                                         \
    for (int q = 0; q < 4; q++) {                                             \
        int r = lr + 16 * q;                                                  \
        pfA[q] = *(const float2*)(pos  + (n0 + r) * DIM + (D0) + 2 * lc2);    \
        pfB[q] = *(const float2*)(Bsrc + (mrow0 + r) * DIM + (D0) + 2 * lc2); \
    }                                                                         \
    if (t < NKP) pfW = *(const float2*)(w3 + (D0) + 2 * t);                   \
} while (0)

    LOADC(0);
    for (int c = 0; c < DIM / DK; c++) {
        __syncthreads();
#pragma unroll
        for (int q = 0; q < 4; q++) {
            int r = lr + 16 * q;
            sA[lc2][r] = pfA[q];
            sB[lc2][r] = pfB[q];
        }
        if (t < NKP) sW2[t] = pfW;
        __syncthreads();
        if (c < DIM / DK - 1) LOADC((c + 1) * DK);

#pragma unroll
        for (int kk = 0; kk < NKP; kk++) {
            ulonglong2 A0 = *(const ulonglong2*)&sA[kk][ty * 4];
            ulonglong2 A1 = *(const ulonglong2*)&sA[kk][ty * 4 + 2];
            ulonglong2 B0 = *(const ulonglong2*)&sB[kk][tx * 4];
            ulonglong2 B1 = *(const ulonglong2*)&sB[kk][tx * 4 + 2];
            unsigned long long a2[4] = {A0.x, A0.y, A1.x, A1.y};
            unsigned long long b2[4] = {B0.x, B0.y, B1.x, B1.y};
            unsigned long long w2 = *(const unsigned long long*)&sW2[kk];
#pragma unroll
            for (int i = 0; i < 4; i++) {
#pragma unroll
                for (int j = 0; j < 4; j++) {
                    dot2[i][j] = ff2(a2[i], b2[j], dot2[i][j]);
                    unsigned long long d = ff2(b2[j], NEG1, a2[i]) & ABSM; // |a-b| packed
                    t32[i][j] = ff2(d, w2, t32[i][j]);
                }
            }
        }
    }

    // ---- epilogue ----
    int gn[4];
    float rn_n[4], t1v[4], rn_m[4], t2v[4];
#pragma unroll
    for (int i = 0; i < 4; i++) {
        gn[i] = n0 + ty * 4 + i;
        rn_n[i] = g_rnorm[gn[i]];
        t1v[i]  = g_t1[gn[i]];
    }
#pragma unroll
    for (int j = 0; j < 4; j++) {
        int gm = m0 + tx * 4 + j;
        rn_m[j] = g_rnorm[gm];
        t2v[j]  = g_t2[gm];
    }
    float bias = __ldg(bptr);

    float part = 0.f;

    if (!pos_half) {
        // ---- negative half: bce + deno ----
        float bce = 0.f, dl[4] = {0.f, 0.f, 0.f, 0.f};
#pragma unroll
        for (int i = 0; i < 4; i++) {
#pragma unroll
            for (int j = 0; j < 4; j++) {
                float dot = lo2(dot2[i][j]) + hi2(dot2[i][j]);
                float t3  = lo2(t32[i][j])  + hi2(t32[i][j]);
                float cc = dot * rn_n[i] * rn_m[j];
                float logit = t1v[i] + t2v[j] + t3 + bias;
                bce += sp(logit);              // label 0
                dl[i] += expf(cc);
            }
        }
#pragma unroll
        for (int i = 0; i < 4; i++) {
            float v = dl[i];
            v += __shfl_xor_sync(0xffffffffu, v, 1);
            v += __shfl_xor_sync(0xffffffffu, v, 2);
            v += __shfl_xor_sync(0xffffffffu, v, 4);
            v += __shfl_xor_sync(0xffffffffu, v, 8);
            if (tx == 0) atomicAdd(&g_deno[gn[i]], v);
        }
        __threadfence();                       // publish deno before negdone arrive
        part = bce * (1.0f / (float)NALL);
    } else {
        // ---- positive half: wait for deno, then bce + contrastive ----
        if (t == 0) {
            while (atomicCAS(&g_negdone, 64u, 64u) != 64u) { __nanosleep(200); }
        }
        __syncthreads();
        __threadfence();
        float dn[4];
#pragma unroll
        for (int i = 0; i < 4; i++) dn[i] = __ldcg(&g_deno[gn[i]]);

        float bce = 0.f, l1 = 0.f;
#pragma unroll
        for (int i = 0; i < 4; i++) {
#pragma unroll
            for (int j = 0; j < 4; j++) {
                float dot = lo2(dot2[i][j]) + hi2(dot2[i][j]);
                float t3  = lo2(t32[i][j])  + hi2(t32[i][j]);
                float cc = dot * rn_n[i] * rn_m[j];
                float logit = t1v[i] + t2v[j] + t3 + bias;
                bce += sp(-logit);             // label 1
                l1 += logf(dn[i] + expf(cc) + EPSV) - cc;   // -log(e^c/(deno+e^c+eps))
            }
        }
        part = bce * (1.0f / (float)NALL) + l1;
    }

    // ---- block reduce + global accumulate + completion protocol ----
    float v = warp_sum(part);
    if ((t & 31) == 0) sRed[t >> 5] = v;
    __syncthreads();
    if (t == 0) {
        float s = 0.f;
#pragma unroll
        for (int k = 0; k < 8; k++) s += sRed[k];
        atomicAdd(&g_total, s);
        __threadfence();
        if (!pos_half) atomicAdd(&g_negdone, 1u);
        unsigned old = atomicAdd(&g_alldone, 1u);
        if (old == 127u) {
            __threadfence();
            out[0] = atomicAdd(&g_total, 0.f);  // all 128 contributions visible
        }
    }
}

// ---------------- launch ----------------
extern "C" void kernel_launch(void* const* d_in, const int* in_sizes, int n_in,
                              void* d_out, int out_size) {
    const float* pos = (const float*)d_in[0];   // [512,512]
    const float* neg = (const float*)d_in[1];   // [512,512]
    const float* w   = (const float*)d_in[2];   // [1,1536]
    const float* b   = (const float*)d_in[3];   // [1]
    float* out = (float*)d_out;

    row_kernel<<<NALL, 128>>>(pos, neg, w);
    dim3 grid(NALL / TILE, NPOS / TILE);        // (16, 8) — one wave, 128 blocks
    pair_kernel<<<grid, 256>>>(pos, neg, w, b, out);
}